// round 12
// baseline (speedup 1.0000x reference)
#include <cuda_runtime.h>
#include <cuda_bf16.h>
#include <math_constants.h>
#include <cstdint>

// Problem constants
#define DIMS    128
#define NQ      2048
#define MBANK   100000
#define KNN     5

// Tiling
#define QT      128               // queries per CTA
#define BT      256               // bank rows per stage (two 128-col halves)
#define NSPLIT  9                 // M splits; 16*9 = 144 CTAs = one wave
#define NTHR    256
#define MS_LEN  11264             // 44 tiles of 256; 9*11264 = 101376 (padded M)
#define PADM    (NSPLIT * MS_LEN)
#define NTILES  (MS_LEN / BT)     // 44

// Dynamic SMEM layout
#define SM_A       0              // 128 x 128 s8 swizzled = 16384 B
#define SM_B       16384          // 2 x 32768 B (double-buffered 256-row tiles)
#define SM_YS      81920          // float2 ybs[2][256] = 4096 B (y2, scale)
#define SM_SX      86016          // float sx[128] (query row scales)
#define SM_MB      86528          // 2 mbarriers
#define SMEM_TOTAL 86560

// Static device scratch. g_bankq: bank quantized to s8, pre-swizzled in
// 256-row x 128B tile blocks (linear cp.async.bulk lands ldmatrix-ready).
__device__ __align__(16) float2 g_ybs[PADM];            // (y2, dequant scale)
__device__ __align__(128) int8_t g_bankq[(size_t)PADM * DIMS];
__device__ float g_part[(size_t)NQ * NSPLIT * KNN];

// ---------------------------------------------------------------------------
// PTX helpers (base-target ISA only)
// ---------------------------------------------------------------------------
__device__ __forceinline__ uint32_t smem_u32(const void* p) {
    uint32_t a;
    asm("{ .reg .u64 t; cvta.to.shared.u64 t, %1; cvt.u32.u64 %0, t; }"
        : "=r"(a) : "l"(p));
    return a;
}
__device__ __forceinline__ void ldsm4(uint32_t& r0, uint32_t& r1,
                                      uint32_t& r2, uint32_t& r3, uint32_t a) {
    asm volatile("ldmatrix.sync.aligned.m8n8.x4.shared.b16 {%0,%1,%2,%3}, [%4];"
                 : "=r"(r0), "=r"(r1), "=r"(r2), "=r"(r3) : "r"(a));
}
__device__ __forceinline__ void imma32(int* c, const uint32_t* a,
                                       const uint32_t* b) {
    asm volatile(
        "mma.sync.aligned.m16n8k32.row.col.s32.s8.s8.s32 "
        "{%0,%1,%2,%3}, {%4,%5,%6,%7}, {%8,%9}, {%0,%1,%2,%3};"
        : "+r"(c[0]), "+r"(c[1]), "+r"(c[2]), "+r"(c[3])
        : "r"(a[0]), "r"(a[1]), "r"(a[2]), "r"(a[3]), "r"(b[0]), "r"(b[1]));
}
__device__ __forceinline__ void mbar_init(uint32_t a, uint32_t cnt) {
    asm volatile("mbarrier.init.shared.b64 [%0], %1;" :: "r"(a), "r"(cnt) : "memory");
}
__device__ __forceinline__ void mbar_expect_tx(uint32_t a, uint32_t tx) {
    asm volatile("mbarrier.arrive.expect_tx.shared.b64 _, [%0], %1;"
                 :: "r"(a), "r"(tx) : "memory");
}
__device__ __forceinline__ void mbar_wait(uint32_t a, int parity) {
    asm volatile(
        "{\n\t.reg .pred P;\n\t"
        "WL%=:\n\t"
        "mbarrier.try_wait.parity.acquire.cta.shared::cta.b64 P, [%0], %1, 0x989680;\n\t"
        "@!P bra WL%=;\n\t}"
        :: "r"(a), "r"(parity) : "memory");
}
__device__ __forceinline__ void bulk_g2s(uint32_t dst, const void* src,
                                         uint32_t bytes, uint32_t mbar) {
    asm volatile(
        "cp.async.bulk.shared::cluster.global.mbarrier::complete_tx::bytes "
        "[%0], [%1], %2, [%3];"
        :: "r"(dst), "l"(src), "r"(bytes), "r"(mbar) : "memory");
}
__device__ __forceinline__ uint32_t pack4(float a, float b, float c, float d) {
    int q0 = __float2int_rn(a), q1 = __float2int_rn(b);
    int q2 = __float2int_rn(c), q3 = __float2int_rn(d);
    return (uint32_t)(q0 & 255) | ((uint32_t)(q1 & 255) << 8) |
           ((uint32_t)(q2 & 255) << 16) | ((uint32_t)q3 << 24);
}

// ---------------------------------------------------------------------------
// Kernel 1: per bank row: y2 (exact fp32), maxabs scale, s8 quantize into
// tile-swizzled gmem. Warp per row. Padding rows: zeros, y2=+INF, scale=0.
// Layout: row m -> tile (m>>8), r = m&255; base = tile*32768 + r*128;
// 16B chunk c goes to base + ((c*16) ^ ((r&7)<<4)).
// ---------------------------------------------------------------------------
__global__ void prep_kernel(const float* __restrict__ bank) {
    int wid  = threadIdx.x >> 5;
    int lane = threadIdx.x & 31;
    int row  = blockIdx.x * (blockDim.x >> 5) + wid;
    if (row >= PADM) return;

    char* dst = reinterpret_cast<char*>(g_bankq)
              + (size_t)(row >> 8) * 32768 + (row & 255) * 128;
    uint32_t swz = (row & 7) << 4;
    uint32_t off = (((uint32_t)(lane >> 2) * 16) ^ swz) + (lane & 3) * 4;

    if (row < MBANK) {
        const float4* p = reinterpret_cast<const float4*>(bank + (size_t)row * DIMS);
        float4 v = p[lane];
        float s = v.x*v.x + v.y*v.y + v.z*v.z + v.w*v.w;
        float a = fmaxf(fmaxf(fabsf(v.x), fabsf(v.y)), fmaxf(fabsf(v.z), fabsf(v.w)));
        #pragma unroll
        for (int o = 16; o; o >>= 1) {
            s += __shfl_xor_sync(0xffffffffu, s, o);
            a  = fmaxf(a, __shfl_xor_sync(0xffffffffu, a, o));
        }
        float inv = (a > 0.f) ? (127.f / a) : 0.f;
        *reinterpret_cast<uint32_t*>(dst + off) =
            pack4(v.x * inv, v.y * inv, v.z * inv, v.w * inv);
        if (lane == 0) g_ybs[row] = make_float2(s, a * (1.f / 127.f));
    } else {
        *reinterpret_cast<uint32_t*>(dst + off) = 0u;
        if (lane == 0) g_ybs[row] = make_float2(CUDART_INF_F, 0.f);
    }
}

// ---------------------------------------------------------------------------
// Kernel 2: s8 warp-IMMA distance GEMM, B staged by cp.async.bulk,
// fused per-query top-5. 8 warps 4(M)x2(N); warp tile 32x64 per half.
// A fragments preloaded once (A constant across all tiles).
// ---------------------------------------------------------------------------
__global__ void __launch_bounds__(NTHR, 1)
knn_mma(const float* __restrict__ feat) {
    extern __shared__ char smem[];
    const uint32_t sb = smem_u32(smem);
    const int tid  = threadIdx.x;
    const int lane = tid & 31;
    const int wid  = tid >> 5;
    const int wm   = wid >> 1;         // 0..3
    const int wn   = wid & 1;          // 0..1
    const int q0   = blockIdx.x * QT;
    const int sp   = blockIdx.y;

    float* sxs = reinterpret_cast<float*>(smem + SM_SX);

    if (tid == 0) {
        mbar_init(sb + SM_MB + 0, 1);
        mbar_init(sb + SM_MB + 8, 1);
    }

    // --- Prologue: quantize A (queries). 2 threads per row (64 elems each),
    // row max combined via shfl (partner = adjacent lane). ---
    {
        int r = tid >> 1, h = tid & 1;
        const float4* src = reinterpret_cast<const float4*>(
            feat + (size_t)(q0 + r) * DIMS + h * 64);
        float4 v[16];
        float a = 0.f;
        #pragma unroll
        for (int i = 0; i < 16; i++) {
            v[i] = src[i];
            a = fmaxf(a, fmaxf(fmaxf(fabsf(v[i].x), fabsf(v[i].y)),
                               fmaxf(fabsf(v[i].z), fabsf(v[i].w))));
        }
        a = fmaxf(a, __shfl_xor_sync(0xffffffffu, a, 1));
        float inv = (a > 0.f) ? (127.f / a) : 0.f;
        if (h == 0) sxs[r] = a * (1.f / 127.f);
        uint32_t rbase = (uint32_t)(r * 128);
        uint32_t swz = (r & 7) << 4;
        #pragma unroll
        for (int g = 0; g < 4; g++) {
            uint4 pk;
            pk.x = pack4(v[g*4+0].x*inv, v[g*4+0].y*inv, v[g*4+0].z*inv, v[g*4+0].w*inv);
            pk.y = pack4(v[g*4+1].x*inv, v[g*4+1].y*inv, v[g*4+1].z*inv, v[g*4+1].w*inv);
            pk.z = pack4(v[g*4+2].x*inv, v[g*4+2].y*inv, v[g*4+2].z*inv, v[g*4+2].w*inv);
            pk.w = pack4(v[g*4+3].x*inv, v[g*4+3].y*inv, v[g*4+3].z*inv, v[g*4+3].w*inv);
            uint32_t kb = (uint32_t)(h * 64 + g * 16);
            *reinterpret_cast<uint4*>(smem + SM_A + rbase + (kb ^ swz)) = pk;
        }
    }
    __syncthreads();   // mbar init + A quantized visible

    // --- bulk stage issuer (thread 0): 32KB B tile + 2KB (y2,scale) ---
    const int tile0 = sp * NTILES;
    auto issue_tile = [&](int t, int buf) {
        uint32_t mb = sb + SM_MB + buf * 8;
        mbar_expect_tx(mb, 32768u + 2048u);
        const char* bsrc = reinterpret_cast<const char*>(g_bankq)
                         + (size_t)(tile0 + t) * 32768;
        bulk_g2s(sb + SM_B + buf * 32768, bsrc, 32768u, mb);
        const char* ysrc = reinterpret_cast<const char*>(g_ybs)
                         + ((size_t)sp * MS_LEN + (size_t)t * BT) * 8;
        bulk_g2s(sb + SM_YS + buf * 2048, ysrc, 2048u, mb);
    };
    if (tid == 0) issue_tile(0, 0);

    // --- Preload ALL A fragments (constant across tiles): 2 m-halves x 4 ks ---
    const int q2 = (lane >> 4) & 1;
    const int rA = wm * 32 + (lane & 7) + ((lane >> 3) & 1) * 8;
    const uint32_t aRow = sb + SM_A + rA * 128;
    const uint32_t swzA = (rA & 7) << 4;
    uint32_t afr[2][4][4];
    #pragma unroll
    for (int ks = 0; ks < 4; ks++) {
        uint32_t ko = (uint32_t)(ks * 32 + q2 * 16);
        ldsm4(afr[0][ks][0], afr[0][ks][1], afr[0][ks][2], afr[0][ks][3],
              aRow + (ko ^ swzA));
        ldsm4(afr[1][ks][0], afr[1][ks][1], afr[1][ks][2], afr[1][ks][3],
              aRow + 2048 + (ko ^ swzA));
    }

    const int nB = wn * 64 + (lane & 7) + ((lane >> 3) & 1) * 8;
    const uint32_t swzB = (nB & 7) << 4;

    // per-thread query-row scales (4 owned rows)
    float sxa[4];
    #pragma unroll
    for (int r = 0; r < 4; r++)
        sxa[r] = sxs[wm * 32 + (r >> 1) * 16 + (r & 1) * 8 + (lane >> 2)];

    // per-thread top-5 for 4 query rows
    float t5[4][KNN], worst[4];
    #pragma unroll
    for (int r = 0; r < 4; r++) {
        worst[r] = CUDART_INF_F;
        #pragma unroll
        for (int u = 0; u < KNN; u++) t5[r][u] = CUDART_INF_F;
    }

    int ph[2] = {0, 0};

    for (int t = 0; t < NTILES; t++) {
        const int idx = t & 1;
        if (t + 1 < NTILES && tid == 0) issue_tile(t + 1, idx ^ 1);

        mbar_wait(sb + SM_MB + idx * 8, ph[idx]);
        ph[idx] ^= 1;

        #pragma unroll
        for (int half = 0; half < 2; half++) {
            const uint32_t bRow = sb + SM_B + idx * 32768 + half * 16384 + nB * 128;
            int acc[2][8][4];
            #pragma unroll
            for (int mf = 0; mf < 2; mf++)
                #pragma unroll
                for (int nf = 0; nf < 8; nf++)
                    #pragma unroll
                    for (int c = 0; c < 4; c++) acc[mf][nf][c] = 0;

            #pragma unroll
            for (int ks = 0; ks < 4; ks++) {
                uint32_t ko = (uint32_t)(ks * 32 + q2 * 16);
                uint32_t bb[8][2];
                #pragma unroll
                for (int p = 0; p < 4; p++) {
                    uint32_t r0, r1, r2, r3;
                    ldsm4(r0, r1, r2, r3, bRow + p * 2048 + (ko ^ swzB));
                    bb[2*p][0] = r0; bb[2*p+1][0] = r1;
                    bb[2*p][1] = r2; bb[2*p+1][1] = r3;
                }
                #pragma unroll
                for (int nf = 0; nf < 8; nf++) {
                    imma32(acc[0][nf], afr[0][ks], bb[nf]);
                    imma32(acc[1][nf], afr[1][ks], bb[nf]);
                }
            }

            // Epilogue: key = y2 - 2*sx*sb*dot; rare insert into top-5
            const float2* ysb = reinterpret_cast<const float2*>(smem + SM_YS)
                              + idx * 256 + half * 128;
            const int c0 = wn * 64 + (lane & 3) * 2;
            #pragma unroll
            for (int nf = 0; nf < 8; nf++) {
                float2 yb0 = ysb[c0 + nf * 8];
                float2 yb1 = ysb[c0 + nf * 8 + 1];
                float f0 = -2.f * yb0.y;
                float f1 = -2.f * yb1.y;
                #pragma unroll
                for (int mf = 0; mf < 2; mf++)
                    #pragma unroll
                    for (int h = 0; h < 2; h++) {
                        const int r = mf * 2 + h;
                        float k0 = fmaf(sxa[r] * f0, (float)acc[mf][nf][h*2+0], yb0.x);
                        float k1 = fmaf(sxa[r] * f1, (float)acc[mf][nf][h*2+1], yb1.x);
                        #pragma unroll
                        for (int e = 0; e < 2; e++) {
                            float key = e ? k1 : k0;
                            if (key < worst[r]) {
                                bool done = false;
                                #pragma unroll
                                for (int u = 0; u < KNN; u++)
                                    if (!done && t5[r][u] == worst[r]) { t5[r][u] = key; done = true; }
                                float w = t5[r][0];
                                #pragma unroll
                                for (int u = 1; u < KNN; u++) w = fmaxf(w, t5[r][u]);
                                worst[r] = w;
                            }
                        }
                    }
            }
        }
        __syncthreads();   // all readers done with buffer idx before reuse
    }

    // --- Block merge: overlay candidate buffer onto B region ---
    float* cand = reinterpret_cast<float*>(smem + SM_B);   // [128][8*KNN]
    const int gid = lane >> 2;
    #pragma unroll
    for (int r = 0; r < 4; r++) {
        int row  = wm * 32 + (r >> 1) * 16 + (r & 1) * 8 + gid;
        int slot = wn * 4 + (lane & 3);
        #pragma unroll
        for (int u = 0; u < KNN; u++)
            cand[row * (8 * KNN) + slot * KNN + u] = t5[r][u];
    }
    __syncthreads();

    if (tid < QT) {
        float best[KNN], w = CUDART_INF_F;
        #pragma unroll
        for (int u = 0; u < KNN; u++) best[u] = CUDART_INF_F;
        for (int i = 0; i < 8 * KNN; i++) {
            float v = cand[tid * (8 * KNN) + i];
            if (v < w) {
                bool done = false;
                #pragma unroll
                for (int u = 0; u < KNN; u++)
                    if (!done && best[u] == w) { best[u] = v; done = true; }
                w = best[0];
                #pragma unroll
                for (int u = 1; u < KNN; u++) w = fmaxf(w, best[u]);
            }
        }
        size_t base = ((size_t)(q0 + tid) * NSPLIT + sp) * KNN;
        #pragma unroll
        for (int u = 0; u < KNN; u++) g_part[base + u] = best[u];
    }
}

// ---------------------------------------------------------------------------
// Kernel 3: merge splits, sqrt + normalize + mean   (thread per query)
// ---------------------------------------------------------------------------
__global__ void knn_final(const float* __restrict__ feat,
                          const float* __restrict__ minv,
                          const float* __restrict__ maxv,
                          float* __restrict__ out) {
    int q = blockIdx.x * blockDim.x + threadIdx.x;
    if (q >= NQ) return;

    const float4* p = reinterpret_cast<const float4*>(feat + (size_t)q * DIMS);
    float x2 = 0.f;
    #pragma unroll
    for (int i = 0; i < DIMS / 4; i++) {
        float4 v = p[i];
        x2 += v.x*v.x + v.y*v.y + v.z*v.z + v.w*v.w;
    }

    float best[KNN], w = CUDART_INF_F;
    #pragma unroll
    for (int t = 0; t < KNN; t++) best[t] = CUDART_INF_F;
    const float* part = g_part + (size_t)q * NSPLIT * KNN;
    for (int i = 0; i < NSPLIT * KNN; i++) {
        float v = part[i];
        if (v < w) {
            bool done = false;
            #pragma unroll
            for (int t = 0; t < KNN; t++)
                if (!done && best[t] == w) { best[t] = v; done = true; }
            w = best[0];
            #pragma unroll
            for (int t = 1; t < KNN; t++) w = fmaxf(w, best[t]);
        }
    }

    float mn = *minv, mx = *maxv;
    float inv = 1.f / (mx - mn);
    float sum = 0.f;
    #pragma unroll
    for (int t = 0; t < KNN; t++) {
        float d2 = x2 + best[t];
        float d  = sqrtf(fmaxf(d2, 0.f));
        sum += (d - mn) * inv;
    }
    out[q] = sum * (1.f / KNN);
}

// ---------------------------------------------------------------------------
extern "C" void kernel_launch(void* const* d_in, const int* in_sizes, int n_in,
                              void* d_out, int out_size) {
    const float* feat = (const float*)d_in[0];   // (2048, 128) f32
    const float* bank = (const float*)d_in[1];   // (100000, 128) f32
    const float* mnv  = (const float*)d_in[2];   // scalar f32
    const float* mxv  = (const float*)d_in[3];   // scalar f32

    static bool attr_done = false;
    if (!attr_done) {
        cudaFuncSetAttribute(knn_mma, cudaFuncAttributeMaxDynamicSharedMemorySize,
                             SMEM_TOTAL);
        attr_done = true;
    }

    prep_kernel<<<(PADM + 7) / 8, 256>>>(bank);

    dim3 grid(NQ / QT, NSPLIT);
    knn_mma<<<grid, NTHR, SMEM_TOTAL>>>(feat);

    knn_final<<<(NQ + 127) / 128, 128>>>(feat, mnv, mxv, (float*)d_out);
}

// round 13
// speedup vs baseline: 1.8641x; 1.8641x over previous
#include <cuda_runtime.h>
#include <cuda_bf16.h>
#include <math_constants.h>
#include <cstdint>

// Problem constants
#define DIMS    128
#define NQ      2048
#define MBANK   100000
#define KNN     5

// Tiling
#define QT      128               // queries per CTA
#define BT      128               // bank rows per tile
#define NSPLIT  18                // M splits; 16*18 = 288 CTAs = 2 waves co-resident
#define NTHR    256
#define MS_LEN  5632              // 44 tiles of 128; 18*5632 = 101376 (padded M)
#define PADM    (NSPLIT * MS_LEN) // 101376
#define NTILES  (MS_LEN / BT)     // 44

// Dynamic SMEM layout
#define SM_A       0              // 128x128 bf16 swizzled = 32768 B
#define SM_B       32768          // 2 x 32768 B (double-buffered bank tile)
#define SM_YS      98304          // float ys[2][128] = 1024 B
#define SM_MB      99328          // 2 mbarriers (16 B)
#define SMEM_TOTAL 99360

// Static device scratch (no allocation allowed).
// g_bankbf holds the bank pre-converted to bf16 AND pre-swizzled in 128-row
// x 256B tile blocks (so a linear cp.async.bulk lands ldmatrix-ready).
__device__ float g_y2[PADM];
__device__ __align__(128) __nv_bfloat16 g_bankbf[(size_t)PADM * DIMS];
__device__ float g_part[(size_t)NQ * NSPLIT * KNN];

// ---------------------------------------------------------------------------
// PTX helpers (base-target ISA only: sm_80/sm_90 features, no tcgen05)
// ---------------------------------------------------------------------------
__device__ __forceinline__ uint32_t smem_u32(const void* p) {
    uint32_t a;
    asm("{ .reg .u64 t; cvta.to.shared.u64 t, %1; cvt.u32.u64 %0, t; }"
        : "=r"(a) : "l"(p));
    return a;
}
__device__ __forceinline__ void ldsm4(uint32_t& r0, uint32_t& r1,
                                      uint32_t& r2, uint32_t& r3, uint32_t a) {
    asm volatile("ldmatrix.sync.aligned.m8n8.x4.shared.b16 {%0,%1,%2,%3}, [%4];"
                 : "=r"(r0), "=r"(r1), "=r"(r2), "=r"(r3) : "r"(a));
}
__device__ __forceinline__ void mma16816(float* c, const uint32_t* a,
                                         const uint32_t* b) {
    asm volatile(
        "mma.sync.aligned.m16n8k16.row.col.f32.bf16.bf16.f32 "
        "{%0,%1,%2,%3}, {%4,%5,%6,%7}, {%8,%9}, {%0,%1,%2,%3};"
        : "+f"(c[0]), "+f"(c[1]), "+f"(c[2]), "+f"(c[3])
        : "r"(a[0]), "r"(a[1]), "r"(a[2]), "r"(a[3]), "r"(b[0]), "r"(b[1]));
}
__device__ __forceinline__ void mbar_init(uint32_t a, uint32_t cnt) {
    asm volatile("mbarrier.init.shared.b64 [%0], %1;" :: "r"(a), "r"(cnt) : "memory");
}
__device__ __forceinline__ void mbar_expect_tx(uint32_t a, uint32_t tx) {
    asm volatile("mbarrier.arrive.expect_tx.shared.b64 _, [%0], %1;"
                 :: "r"(a), "r"(tx) : "memory");
}
__device__ __forceinline__ void mbar_wait(uint32_t a, int parity) {
    asm volatile(
        "{\n\t.reg .pred P;\n\t"
        "WL%=:\n\t"
        "mbarrier.try_wait.parity.acquire.cta.shared::cta.b64 P, [%0], %1, 0x989680;\n\t"
        "@!P bra WL%=;\n\t}"
        :: "r"(a), "r"(parity) : "memory");
}
__device__ __forceinline__ void bulk_g2s(uint32_t dst, const void* src,
                                         uint32_t bytes, uint32_t mbar) {
    asm volatile(
        "cp.async.bulk.shared::cluster.global.mbarrier::complete_tx::bytes "
        "[%0], [%1], %2, [%3];"
        :: "r"(dst), "l"(src), "r"(bytes), "r"(mbar) : "memory");
}

// ---------------------------------------------------------------------------
// Kernel 1: y2 + fp32->bf16 conversion into tile-swizzled gmem layout.
// Warp per row. Rows >= MBANK (padding): zero data, +INF y2.
// Layout: row m -> tile (m>>7), r = m&127; byte base = tile*32768 + r*256;
// 8B chunk at kb = lane*8 goes to base + (kb ^ ((r&7)<<4)).
// ---------------------------------------------------------------------------
__global__ void prep_kernel(const float* __restrict__ bank) {
    int wid  = threadIdx.x >> 5;
    int lane = threadIdx.x & 31;
    int row  = blockIdx.x * (blockDim.x >> 5) + wid;
    if (row >= PADM) return;

    char* dst_base = reinterpret_cast<char*>(g_bankbf)
                   + (size_t)(row >> 7) * 32768 + (row & 127) * 256;
    uint32_t swz = (row & 7) << 4;
    uint32_t off = ((uint32_t)(lane * 8)) ^ swz;

    if (row < MBANK) {
        const float4* p = reinterpret_cast<const float4*>(bank + (size_t)row * DIMS);
        float4 v = p[lane];
        float s = v.x*v.x + v.y*v.y + v.z*v.z + v.w*v.w;
        __nv_bfloat162 h0 = __floats2bfloat162_rn(v.x, v.y);
        __nv_bfloat162 h1 = __floats2bfloat162_rn(v.z, v.w);
        uint2 packed;
        packed.x = *reinterpret_cast<uint32_t*>(&h0);
        packed.y = *reinterpret_cast<uint32_t*>(&h1);
        *reinterpret_cast<uint2*>(dst_base + off) = packed;
        #pragma unroll
        for (int o = 16; o; o >>= 1) s += __shfl_xor_sync(0xffffffffu, s, o);
        if (lane == 0) g_y2[row] = s;
    } else {
        *reinterpret_cast<uint2*>(dst_base + off) = make_uint2(0u, 0u);
        if (lane == 0) g_y2[row] = CUDART_INF_F;
    }
}

// ---------------------------------------------------------------------------
// Kernel 2: bf16 warp-MMA distance GEMM, B tiles fed by cp.async.bulk,
// fused per-query top-5. 8 warps 4(M)x2(N), warp tile 32x64, acc in regs.
// 2 CTAs co-resident per SM (NSPLIT=18) to hide HMMA/LDSM latency + sync
// bubbles.
// ---------------------------------------------------------------------------
__global__ void __launch_bounds__(NTHR, 2)
knn_mma(const float* __restrict__ feat) {
    extern __shared__ char smem[];
    const uint32_t sb = smem_u32(smem);
    const int tid  = threadIdx.x;
    const int lane = tid & 31;
    const int wid  = tid >> 5;
    const int wm   = wid >> 1;         // 0..3
    const int wn   = wid & 1;          // 0..1
    const int q0   = blockIdx.x * QT;
    const int sp   = blockIdx.y;

    float* ys = reinterpret_cast<float*>(smem + SM_YS);

    if (tid == 0) {
        mbar_init(sb + SM_MB + 0, 1);
        mbar_init(sb + SM_MB + 8, 1);
    }

    // --- Prologue: A tile (queries) fp32 -> bf16, XOR-swizzled in SMEM ---
    {
        int r = tid >> 1, half = tid & 1;
        uint32_t swz = (r & 7) << 4;
        const float2* src = reinterpret_cast<const float2*>(
            feat + (size_t)(q0 + r) * DIMS + half * 64);
        #pragma unroll
        for (int j = 0; j < 32; j += 2) {
            float2 f0 = src[j], f1 = src[j + 1];
            __nv_bfloat162 h0 = __floats2bfloat162_rn(f0.x, f0.y);
            __nv_bfloat162 h1 = __floats2bfloat162_rn(f1.x, f1.y);
            uint32_t kb = half * 128 + j * 4;
            uint2 pk;
            pk.x = *reinterpret_cast<uint32_t*>(&h0);
            pk.y = *reinterpret_cast<uint32_t*>(&h1);
            *reinterpret_cast<uint2*>(smem + SM_A + r * 256 + (kb ^ swz)) = pk;
        }
    }
    __syncthreads();   // mbarriers initialized + A visible before any bulk waits

    // --- bulk B-tile issuer (thread 0 only): 32KB tile + 512B y2 slice ---
    const int tile0 = sp * NTILES;     // global 128-row tile index base
    auto issue_tile = [&](int t, int buf) {
        uint32_t mb = sb + SM_MB + buf * 8;
        mbar_expect_tx(mb, 32768u + 512u);
        const char* bsrc = reinterpret_cast<const char*>(g_bankbf)
                         + (size_t)(tile0 + t) * 32768;
        bulk_g2s(sb + SM_B + buf * 32768, bsrc, 32768u, mb);
        const char* ysrc = reinterpret_cast<const char*>(g_y2)
                         + ((size_t)sp * MS_LEN + (size_t)t * BT) * 4;
        bulk_g2s(sb + SM_YS + buf * 512, ysrc, 512u, mb);
    };
    if (tid == 0) issue_tile(0, 0);

    // ldmatrix lane address components (fixed per thread)
    const int q2   = (lane >> 4) & 1;
    const int rA   = wm * 32 + (lane & 7) + ((lane >> 3) & 1) * 8;
    const uint32_t aRow = sb + SM_A + rA * 256;
    const uint32_t swzA = (rA & 7) << 4;
    const int nB   = wn * 64 + (lane & 7) + ((lane >> 3) & 1) * 8;
    const uint32_t swzB = (nB & 7) << 4;

    // per-thread top-5 for 4 query rows
    float t5[4][KNN], worst[4];
    #pragma unroll
    for (int r = 0; r < 4; r++) {
        worst[r] = CUDART_INF_F;
        #pragma unroll
        for (int u = 0; u < KNN; u++) t5[r][u] = CUDART_INF_F;
    }

    int ph[2] = {0, 0};

    for (int t = 0; t < NTILES; t++) {
        const int idx = t & 1;
        // issue next tile into the other buffer (its previous readers finished
        // at the __syncthreads() ending iteration t-1)
        if (t + 1 < NTILES && tid == 0) issue_tile(t + 1, idx ^ 1);

        mbar_wait(sb + SM_MB + idx * 8, ph[idx]);
        ph[idx] ^= 1;

        const uint32_t bRow = sb + SM_B + idx * 32768 + nB * 256;
        float acc[2][8][4];
        #pragma unroll
        for (int mf = 0; mf < 2; mf++)
            #pragma unroll
            for (int nf = 0; nf < 8; nf++)
                #pragma unroll
                for (int c = 0; c < 4; c++) acc[mf][nf][c] = 0.f;

        #pragma unroll
        for (int ks = 0; ks < 8; ks++) {
            uint32_t ko = (uint32_t)(ks * 32 + q2 * 16);
            uint32_t a0[4], a1[4];
            ldsm4(a0[0], a0[1], a0[2], a0[3], aRow + (ko ^ swzA));
            ldsm4(a1[0], a1[1], a1[2], a1[3], aRow + 4096 + (ko ^ swzA));
            uint32_t bb[8][2];
            #pragma unroll
            for (int p = 0; p < 4; p++) {
                uint32_t r0, r1, r2, r3;
                ldsm4(r0, r1, r2, r3, bRow + p * 4096 + (ko ^ swzB));
                bb[2*p][0] = r0; bb[2*p+1][0] = r1;
                bb[2*p][1] = r2; bb[2*p+1][1] = r3;
            }
            #pragma unroll
            for (int nf = 0; nf < 8; nf++) {
                mma16816(acc[0][nf], a0, bb[nf]);
                mma16816(acc[1][nf], a1, bb[nf]);
            }
        }

        // Epilogue: key = y2 - 2*dot, rare insert into per-thread top-5
        const float* ysb = ys + idx * BT;
        const int c0 = wn * 64 + (lane & 3) * 2;
        #pragma unroll
        for (int nf = 0; nf < 8; nf++) {
            float y0 = ysb[c0 + nf * 8];
            float y1 = ysb[c0 + nf * 8 + 1];
            #pragma unroll
            for (int mf = 0; mf < 2; mf++)
                #pragma unroll
                for (int h = 0; h < 2; h++) {
                    const int r = mf * 2 + h;
                    float k0 = fmaf(-2.f, acc[mf][nf][h * 2 + 0], y0);
                    float k1 = fmaf(-2.f, acc[mf][nf][h * 2 + 1], y1);
                    #pragma unroll
                    for (int e = 0; e < 2; e++) {
                        float key = e ? k1 : k0;
                        if (key < worst[r]) {
                            bool done = false;
                            #pragma unroll
                            for (int u = 0; u < KNN; u++)
                                if (!done && t5[r][u] == worst[r]) { t5[r][u] = key; done = true; }
                            float w = t5[r][0];
                            #pragma unroll
                            for (int u = 1; u < KNN; u++) w = fmaxf(w, t5[r][u]);
                            worst[r] = w;
                        }
                    }
                }
        }
        __syncthreads();   // all readers done with buffer idx before reuse
    }

    // --- Block merge: overlay candidate buffer onto B region ---
    float* cand = reinterpret_cast<float*>(smem + SM_B);   // [128][8*KNN]
    const int gid = lane >> 2;
    #pragma unroll
    for (int r = 0; r < 4; r++) {
        int row  = wm * 32 + (r >> 1) * 16 + (r & 1) * 8 + gid;
        int slot = wn * 4 + (lane & 3);
        #pragma unroll
        for (int u = 0; u < KNN; u++)
            cand[row * (8 * KNN) + slot * KNN + u] = t5[r][u];
    }
    __syncthreads();

    if (tid < QT) {
        float best[KNN], w = CUDART_INF_F;
        #pragma unroll
        for (int u = 0; u < KNN; u++) best[u] = CUDART_INF_F;
        for (int i = 0; i < 8 * KNN; i++) {
            float v = cand[tid * (8 * KNN) + i];
            if (v < w) {
                bool done = false;
                #pragma unroll
                for (int u = 0; u < KNN; u++)
                    if (!done && best[u] == w) { best[u] = v; done = true; }
                w = best[0];
                #pragma unroll
                for (int u = 1; u < KNN; u++) w = fmaxf(w, best[u]);
            }
        }
        size_t base = ((size_t)(q0 + tid) * NSPLIT + sp) * KNN;
        #pragma unroll
        for (int u = 0; u < KNN; u++) g_part[base + u] = best[u];
    }
}

// ---------------------------------------------------------------------------
// Kernel 3: merge splits, sqrt + normalize + mean   (thread per query)
// ---------------------------------------------------------------------------
__global__ void knn_final(const float* __restrict__ feat,
                          const float* __restrict__ minv,
                          const float* __restrict__ maxv,
                          float* __restrict__ out) {
    int q = blockIdx.x * blockDim.x + threadIdx.x;
    if (q >= NQ) return;

    const float4* p = reinterpret_cast<const float4*>(feat + (size_t)q * DIMS);
    float x2 = 0.f;
    #pragma unroll
    for (int i = 0; i < DIMS / 4; i++) {
        float4 v = p[i];
        x2 += v.x*v.x + v.y*v.y + v.z*v.z + v.w*v.w;
    }

    float best[KNN], w = CUDART_INF_F;
    #pragma unroll
    for (int t = 0; t < KNN; t++) best[t] = CUDART_INF_F;
    const float* part = g_part + (size_t)q * NSPLIT * KNN;
    for (int i = 0; i < NSPLIT * KNN; i++) {
        float v = part[i];
        if (v < w) {
            bool done = false;
            #pragma unroll
            for (int t = 0; t < KNN; t++)
                if (!done && best[t] == w) { best[t] = v; done = true; }
            w = best[0];
            #pragma unroll
            for (int t = 1; t < KNN; t++) w = fmaxf(w, best[t]);
        }
    }

    float mn = *minv, mx = *maxv;
    float inv = 1.f / (mx - mn);
    float sum = 0.f;
    #pragma unroll
    for (int t = 0; t < KNN; t++) {
        float d2 = x2 + best[t];
        float d  = sqrtf(fmaxf(d2, 0.f));
        sum += (d - mn) * inv;
    }
    out[q] = sum * (1.f / KNN);
}

// ---------------------------------------------------------------------------
extern "C" void kernel_launch(void* const* d_in, const int* in_sizes, int n_in,
                              void* d_out, int out_size) {
    const float* feat = (const float*)d_in[0];   // (2048, 128) f32
    const float* bank = (const float*)d_in[1];   // (100000, 128) f32
    const float* mnv  = (const float*)d_in[2];   // scalar f32
    const float* mxv  = (const float*)d_in[3];   // scalar f32

    static bool attr_done = false;
    if (!attr_done) {
        cudaFuncSetAttribute(knn_mma, cudaFuncAttributeMaxDynamicSharedMemorySize,
                             SMEM_TOTAL);
        attr_done = true;
    }

    prep_kernel<<<(PADM + 7) / 8, 256>>>(bank);

    dim3 grid(NQ / QT, NSPLIT);
    knn_mma<<<grid, NTHR, SMEM_TOTAL>>>(feat);

    knn_final<<<(NQ + 127) / 128, 128>>>(feat, mnv, mxv, (float*)d_out);
}

// round 15
// speedup vs baseline: 2.0322x; 1.0902x over previous
#include <cuda_runtime.h>
#include <cuda_bf16.h>
#include <math_constants.h>
#include <cstdint>

// Problem constants
#define DIMS    128
#define NQ      2048
#define MBANK   100000
#define KNN     5

// Tiling
#define QT      128               // queries per CTA
#define BT      64                // bank rows per tile
#define NBUF    4                 // pipeline depth
#define NSPLIT  18                // M splits; 16*18 = 288 CTAs, 2 per SM
#define NTHR    256
#define MS_LEN  5632              // 88 tiles of 64; 18*5632 = 101376 (padded M)
#define PADM    (NSPLIT * MS_LEN) // 101376
#define NTILES  (MS_LEN / BT)     // 88

// Dynamic SMEM layout
#define SM_A       0              // 128x128 bf16 swizzled = 32768 B
#define SM_B       32768          // 4 x 16384 B (quad-buffered 64-row tiles)
#define SM_YS      98304          // float ys[4][64] = 1024 B
#define SM_MB      99328          // full[4] then free[4] mbarriers = 64 B
#define SMEM_TOTAL 99392

// Static device scratch. g_bankbf: bank pre-converted to bf16, pre-swizzled
// in 64-row x 256B tile blocks (linear cp.async.bulk lands ldmatrix-ready).
__device__ float g_y2[PADM];
__device__ __align__(128) __nv_bfloat16 g_bankbf[(size_t)PADM * DIMS];
__device__ float g_part[(size_t)NQ * NSPLIT * KNN];

// ---------------------------------------------------------------------------
// PTX helpers (base-target ISA only)
// ---------------------------------------------------------------------------
__device__ __forceinline__ uint32_t smem_u32(const void* p) {
    uint32_t a;
    asm("{ .reg .u64 t; cvta.to.shared.u64 t, %1; cvt.u32.u64 %0, t; }"
        : "=r"(a) : "l"(p));
    return a;
}
__device__ __forceinline__ void ldsm4(uint32_t& r0, uint32_t& r1,
                                      uint32_t& r2, uint32_t& r3, uint32_t a) {
    asm volatile("ldmatrix.sync.aligned.m8n8.x4.shared.b16 {%0,%1,%2,%3}, [%4];"
                 : "=r"(r0), "=r"(r1), "=r"(r2), "=r"(r3) : "r"(a));
}
__device__ __forceinline__ void mma16816(float* c, const uint32_t* a,
                                         const uint32_t* b) {
    asm volatile(
        "mma.sync.aligned.m16n8k16.row.col.f32.bf16.bf16.f32 "
        "{%0,%1,%2,%3}, {%4,%5,%6,%7}, {%8,%9}, {%0,%1,%2,%3};"
        : "+f"(c[0]), "+f"(c[1]), "+f"(c[2]), "+f"(c[3])
        : "r"(a[0]), "r"(a[1]), "r"(a[2]), "r"(a[3]), "r"(b[0]), "r"(b[1]));
}
__device__ __forceinline__ void mbar_init(uint32_t a, uint32_t cnt) {
    asm volatile("mbarrier.init.shared.b64 [%0], %1;" :: "r"(a), "r"(cnt) : "memory");
}
__device__ __forceinline__ void mbar_expect_tx(uint32_t a, uint32_t tx) {
    asm volatile("mbarrier.arrive.expect_tx.shared.b64 _, [%0], %1;"
                 :: "r"(a), "r"(tx) : "memory");
}
__device__ __forceinline__ void mbar_arrive(uint32_t a) {
    asm volatile("mbarrier.arrive.release.cta.shared.b64 _, [%0];"
                 :: "r"(a) : "memory");
}
__device__ __forceinline__ void mbar_wait(uint32_t a, int parity) {
    asm volatile(
        "{\n\t.reg .pred P;\n\t"
        "WL%=:\n\t"
        "mbarrier.try_wait.parity.acquire.cta.shared::cta.b64 P, [%0], %1, 0x989680;\n\t"
        "@!P bra WL%=;\n\t}"
        :: "r"(a), "r"(parity) : "memory");
}
__device__ __forceinline__ void bulk_g2s(uint32_t dst, const void* src,
                                         uint32_t bytes, uint32_t mbar) {
    asm volatile(
        "cp.async.bulk.shared::cluster.global.mbarrier::complete_tx::bytes "
        "[%0], [%1], %2, [%3];"
        :: "r"(dst), "l"(src), "r"(bytes), "r"(mbar) : "memory");
}

// ---------------------------------------------------------------------------
// Kernel 1: y2 + fp32->bf16 conversion into 64-row tile-swizzled gmem layout.
// Warp per row. Rows >= MBANK (padding): zero data, +INF y2.
// row m -> block (m>>6), r = m&63; byte base = block*16384 + r*256;
// 8B chunk at kb = lane*8 goes to base + (kb ^ ((r&7)<<4)).
// ---------------------------------------------------------------------------
__global__ void prep_kernel(const float* __restrict__ bank) {
    int wid  = threadIdx.x >> 5;
    int lane = threadIdx.x & 31;
    int row  = blockIdx.x * (blockDim.x >> 5) + wid;
    if (row >= PADM) return;

    char* dst_base = reinterpret_cast<char*>(g_bankbf)
                   + (size_t)(row >> 6) * 16384 + (row & 63) * 256;
    uint32_t swz = (row & 7) << 4;
    uint32_t off = ((uint32_t)(lane * 8)) ^ swz;

    if (row < MBANK) {
        const float4* p = reinterpret_cast<const float4*>(bank + (size_t)row * DIMS);
        float4 v = p[lane];
        float s = v.x*v.x + v.y*v.y + v.z*v.z + v.w*v.w;
        __nv_bfloat162 h0 = __floats2bfloat162_rn(v.x, v.y);
        __nv_bfloat162 h1 = __floats2bfloat162_rn(v.z, v.w);
        uint2 packed;
        packed.x = *reinterpret_cast<uint32_t*>(&h0);
        packed.y = *reinterpret_cast<uint32_t*>(&h1);
        *reinterpret_cast<uint2*>(dst_base + off) = packed;
        #pragma unroll
        for (int o = 16; o; o >>= 1) s += __shfl_xor_sync(0xffffffffu, s, o);
        if (lane == 0) g_y2[row] = s;
    } else {
        *reinterpret_cast<uint2*>(dst_base + off) = make_uint2(0u, 0u);
        if (lane == 0) g_y2[row] = CUDART_INF_F;
    }
}

// ---------------------------------------------------------------------------
// Kernel 2: bf16 warp-MMA distance GEMM, 4-deep bulk-copy pipeline with
// producer/consumer mbarriers (no per-tile block barrier), fused top-5.
// 8 warps 4(M)x2(N), warp tile 32x32, acc in regs. 2 CTAs/SM.
// Protocol: producer (tid 0) leads by 3 tiles; free-wait ONLY when a buffer
// is reused (tile index >= NBUF) — waiting on a never-filled buffer deadlocks.
// ---------------------------------------------------------------------------
__global__ void __launch_bounds__(NTHR, 2)
knn_mma(const float* __restrict__ feat) {
    extern __shared__ char smem[];
    const uint32_t sb = smem_u32(smem);
    const int tid  = threadIdx.x;
    const int lane = tid & 31;
    const int wid  = tid >> 5;
    const int wm   = wid >> 1;         // 0..3
    const int wn   = wid & 1;          // 0..1
    const int q0   = blockIdx.x * QT;
    const int sp   = blockIdx.y;

    float* ys = reinterpret_cast<float*>(smem + SM_YS);

    if (tid == 0) {
        #pragma unroll
        for (int b = 0; b < NBUF; b++) {
            mbar_init(sb + SM_MB + b * 8, 1);              // full[b]
            mbar_init(sb + SM_MB + 32 + b * 8, NTHR);      // free[b]
        }
    }

    // --- Prologue: A tile (queries) fp32 -> bf16, XOR-swizzled in SMEM ---
    {
        int r = tid >> 1, half = tid & 1;
        uint32_t swz = (r & 7) << 4;
        const float2* src = reinterpret_cast<const float2*>(
            feat + (size_t)(q0 + r) * DIMS + half * 64);
        #pragma unroll
        for (int j = 0; j < 32; j += 2) {
            float2 f0 = src[j], f1 = src[j + 1];
            __nv_bfloat162 h0 = __floats2bfloat162_rn(f0.x, f0.y);
            __nv_bfloat162 h1 = __floats2bfloat162_rn(f1.x, f1.y);
            uint32_t kb = half * 128 + j * 4;
            uint2 pk;
            pk.x = *reinterpret_cast<uint32_t*>(&h0);
            pk.y = *reinterpret_cast<uint32_t*>(&h1);
            *reinterpret_cast<uint2*>(smem + SM_A + r * 256 + (kb ^ swz)) = pk;
        }
    }
    __syncthreads();   // mbarriers initialized + A visible

    // --- bulk tile issuer (thread 0): 16KB B tile + 256B y2 slice ---
    const int tile0 = sp * NTILES;
    auto issue_tile = [&](int t) {
        int buf = t & (NBUF - 1);
        uint32_t mb = sb + SM_MB + buf * 8;
        mbar_expect_tx(mb, 16384u + 256u);
        const char* bsrc = reinterpret_cast<const char*>(g_bankbf)
                         + (size_t)(tile0 + t) * 16384;
        bulk_g2s(sb + SM_B + buf * 16384, bsrc, 16384u, mb);
        const char* ysrc = reinterpret_cast<const char*>(g_y2)
                         + ((size_t)sp * MS_LEN + (size_t)t * BT) * 4;
        bulk_g2s(sb + SM_YS + buf * 256, ysrc, 256u, mb);
    };
    if (tid == 0) {
        issue_tile(0); issue_tile(1); issue_tile(2);
    }

    // ldmatrix lane address components (fixed per thread)
    const int q2   = (lane >> 4) & 1;
    const int rA   = wm * 32 + (lane & 7) + ((lane >> 3) & 1) * 8;
    const uint32_t aRow = sb + SM_A + rA * 256;
    const uint32_t swzA = (rA & 7) << 4;
    const int nB   = wn * 32 + (lane & 7) + ((lane >> 3) & 1) * 8;
    const uint32_t swzB = (nB & 7) << 4;

    // per-thread top-5 for 4 query rows
    float t5[4][KNN], worst[4];
    #pragma unroll
    for (int r = 0; r < 4; r++) {
        worst[r] = CUDART_INF_F;
        #pragma unroll
        for (int u = 0; u < KNN; u++) t5[r][u] = CUDART_INF_F;
    }

    int ph_full[NBUF] = {0, 0, 0, 0};
    int ph_free[NBUF] = {0, 0, 0, 0};

    for (int t = 0; t < NTILES; t++) {
        const int buf = t & (NBUF - 1);

        // Producer: issue tile t+3. Wait for drain ONLY on buffer reuse
        // (j >= NBUF); the first NBUF tiles enter virgin buffers.
        if (tid == 0 && t + 3 < NTILES) {
            int j = t + 3, jb = j & (NBUF - 1);
            if (j >= NBUF) {
                mbar_wait(sb + SM_MB + 32 + jb * 8, ph_free[jb]);
                ph_free[jb] ^= 1;
            }
            issue_tile(j);
        }

        mbar_wait(sb + SM_MB + buf * 8, ph_full[buf]);
        ph_full[buf] ^= 1;

        const uint32_t bRow = sb + SM_B + buf * 16384 + nB * 256;
        float acc[2][4][4];
        #pragma unroll
        for (int mf = 0; mf < 2; mf++)
            #pragma unroll
            for (int nf = 0; nf < 4; nf++)
                #pragma unroll
                for (int c = 0; c < 4; c++) acc[mf][nf][c] = 0.f;

        #pragma unroll
        for (int ks = 0; ks < 8; ks++) {
            uint32_t ko = (uint32_t)(ks * 32 + q2 * 16);
            uint32_t a0[4], a1[4];
            ldsm4(a0[0], a0[1], a0[2], a0[3], aRow + (ko ^ swzA));
            ldsm4(a1[0], a1[1], a1[2], a1[3], aRow + 4096 + (ko ^ swzA));
            uint32_t bb[4][2];
            #pragma unroll
            for (int p = 0; p < 2; p++) {
                uint32_t r0, r1, r2, r3;
                ldsm4(r0, r1, r2, r3, bRow + p * 4096 + (ko ^ swzB));
                bb[2*p][0] = r0; bb[2*p+1][0] = r1;
                bb[2*p][1] = r2; bb[2*p+1][1] = r3;
            }
            #pragma unroll
            for (int nf = 0; nf < 4; nf++) {
                mma16816(acc[0][nf], a0, bb[nf]);
                mma16816(acc[1][nf], a1, bb[nf]);
            }
        }

        // Epilogue: key = y2 - 2*dot, rare insert into per-thread top-5
        const float* ysb = ys + buf * BT;
        const int c0 = wn * 32 + (lane & 3) * 2;
        #pragma unroll
        for (int nf = 0; nf < 4; nf++) {
            float y0 = ysb[c0 + nf * 8];
            float y1 = ysb[c0 + nf * 8 + 1];
            #pragma unroll
            for (int mf = 0; mf < 2; mf++)
                #pragma unroll
                for (int h = 0; h < 2; h++) {
                    const int r = mf * 2 + h;
                    float k0 = fmaf(-2.f, acc[mf][nf][h * 2 + 0], y0);
                    float k1 = fmaf(-2.f, acc[mf][nf][h * 2 + 1], y1);
                    #pragma unroll
                    for (int e = 0; e < 2; e++) {
                        float key = e ? k1 : k0;
                        if (key < worst[r]) {
                            bool done = false;
                            #pragma unroll
                            for (int u = 0; u < KNN; u++)
                                if (!done && t5[r][u] == worst[r]) { t5[r][u] = key; done = true; }
                            float w = t5[r][0];
                            #pragma unroll
                            for (int u = 1; u < KNN; u++) w = fmaxf(w, t5[r][u]);
                            worst[r] = w;
                        }
                    }
                }
        }

        // Consumer done with this buffer
        mbar_arrive(sb + SM_MB + 32 + buf * 8);
    }

    __syncthreads();   // all consumption done before overlaying cand on B

    // --- Block merge: overlay candidate buffer onto B region ---
    float* cand = reinterpret_cast<float*>(smem + SM_B);   // [128][8*KNN]
    const int gid = lane >> 2;
    #pragma unroll
    for (int r = 0; r < 4; r++) {
        int row  = wm * 32 + (r >> 1) * 16 + (r & 1) * 8 + gid;
        int slot = wn * 4 + (lane & 3);
        #pragma unroll
        for (int u = 0; u < KNN; u++)
            cand[row * (8 * KNN) + slot * KNN + u] = t5[r][u];
    }
    __syncthreads();

    if (tid < QT) {
        float best[KNN], w = CUDART_INF_F;
        #pragma unroll
        for (int u = 0; u < KNN; u++) best[u] = CUDART_INF_F;
        for (int i = 0; i < 8 * KNN; i++) {
            float v = cand[tid * (8 * KNN) + i];
            if (v < w) {
                bool done = false;
                #pragma unroll
                for (int u = 0; u < KNN; u++)
                    if (!done && best[u] == w) { best[u] = v; done = true; }
                w = best[0];
                #pragma unroll
                for (int u = 1; u < KNN; u++) w = fmaxf(w, best[u]);
            }
        }
        size_t base = ((size_t)(q0 + tid) * NSPLIT + sp) * KNN;
        #pragma unroll
        for (int u = 0; u < KNN; u++) g_part[base + u] = best[u];
    }
}

// ---------------------------------------------------------------------------
// Kernel 3: merge splits, sqrt + normalize + mean   (thread per query)
// ---------------------------------------------------------------------------
__global__ void knn_final(const float* __restrict__ feat,
                          const float* __restrict__ minv,
                          const float* __restrict__ maxv,
                          float* __restrict__ out) {
    int q = blockIdx.x * blockDim.x + threadIdx.x;
    if (q >= NQ) return;

    const float4* p = reinterpret_cast<const float4*>(feat + (size_t)q * DIMS);
    float x2 = 0.f;
    #pragma unroll
    for (int i = 0; i < DIMS / 4; i++) {
        float4 v = p[i];
        x2 += v.x*v.x + v.y*v.y + v.z*v.z + v.w*v.w;
    }

    float best[KNN], w = CUDART_INF_F;
    #pragma unroll
    for (int t = 0; t < KNN; t++) best[t] = CUDART_INF_F;
    const float* part = g_part + (size_t)q * NSPLIT * KNN;
    for (int i = 0; i < NSPLIT * KNN; i++) {
        float v = part[i];
        if (v < w) {
            bool done = false;
            #pragma unroll
            for (int t = 0; t < KNN; t++)
                if (!done && best[t] == w) { best[t] = v; done = true; }
            w = best[0];
            #pragma unroll
            for (int t = 1; t < KNN; t++) w = fmaxf(w, best[t]);
        }
    }

    float mn = *minv, mx = *maxv;
    float inv = 1.f / (mx - mn);
    float sum = 0.f;
    #pragma unroll
    for (int t = 0; t < KNN; t++) {
        float d2 = x2 + best[t];
        float d  = sqrtf(fmaxf(d2, 0.f));
        sum += (d - mn) * inv;
    }
    out[q] = sum * (1.f / KNN);
}

// ---------------------------------------------------------------------------
extern "C" void kernel_launch(void* const* d_in, const int* in_sizes, int n_in,
                              void* d_out, int out_size) {
    const float* feat = (const float*)d_in[0];   // (2048, 128) f32
    const float* bank = (const float*)d_in[1];   // (100000, 128) f32
    const float* mnv  = (const float*)d_in[2];   // scalar f32
    const float* mxv  = (const float*)d_in[3];   // scalar f32

    static bool attr_done = false;
    if (!attr_done) {
        cudaFuncSetAttribute(knn_mma, cudaFuncAttributeMaxDynamicSharedMemorySize,
                             SMEM_TOTAL);
        attr_done = true;
    }

    prep_kernel<<<(PADM + 7) / 8, 256>>>(bank);

    dim3 grid(NQ / QT, NSPLIT);
    knn_mma<<<grid, NTHR, SMEM_TOTAL>>>(feat);

    knn_final<<<(NQ + 127) / 128, 128>>>(feat, mnv, mxv, (float*)d_out);
}